// round 16
// baseline (speedup 1.0000x reference)
#include <cuda_runtime.h>
#include <cuda_bf16.h>
#include <cstdint>
#include <math.h>

// ---------------------------------------------------------------------------
// QLayer_Block round 16: bf16 HMMA GEMMs (exact integer math).
// New vs r15: attn GEMM's 4th m-tile (rows 192-255, only 4 real) removed;
// main GEMM covers rows 0-191 and a small exact-FMA tail kernel computes
// tokens 192-195 (f32 FMA on integer-valued bf16 is exact -> bit-identical).
// Keeps: fast-div fqq (r14), GELU LUT (r15), per-stage GEMM configs (r11).
// ---------------------------------------------------------------------------

namespace {

typedef __nv_bfloat16 bf16;
typedef __nv_bfloat162 bf162;

constexpr int BATCH = 128;
constexpr int NTOK  = 196;
constexpr int DIM   = 768;
constexpr int HID   = 3072;
constexpr int RNK   = 384;
constexpr int KPAD  = 256;
constexpr long TROWS = (long)BATCH * NTOK;   // 25088

// ---- device scratch (integer-valued bf16) ----
__device__ __align__(256) bf16 g_qWattn[256 * KPAD];
__device__ __align__(256) bf16 g_qW1vt[RNK * DIM];
__device__ __align__(256) bf16 g_qW1u [HID * RNK];
__device__ __align__(256) bf16 g_qW2vt[RNK * HID];
__device__ __align__(256) bf16 g_qW2u [DIM * RNK];

__device__ __align__(256) float g_v1a[DIM];
__device__ __align__(256) float g_v2a[DIM];
__device__ __align__(256) float g_g1 [DIM];
__device__ __align__(256) float g_g2 [DIM];
__device__ float g_absmax[8];
__device__ __align__(256) unsigned short g_gelut[256];   // bf16 bits of fq(gelu)

__device__ __align__(256) bf16 g_qa1t[(long)BATCH * DIM * KPAD]; // [b][d][npad]
__device__ __align__(256) bf16 g_qx1 [TROWS * DIM];
__device__ __align__(256) bf16 g_qa2 [TROWS * DIM];
__device__ __align__(256) bf16 g_qa3 [TROWS * RNK];
__device__ __align__(256) bf16 g_qa4 [TROWS * HID];
__device__ __align__(256) bf16 g_qa5 [TROWS * RNK];

// exact fqq (prep paths only)
__device__ __forceinline__ float fqq(float x, float s) {
    float r = rintf(__fdiv_rn(x, s));
    return fminf(127.f, fmaxf(-128.f, r));
}
__device__ __forceinline__ float wscale(int slot) {
    return __fadd_rn(__fdiv_rn(g_absmax[slot], 127.f), 1e-8f);
}

// Newton-refined reciprocal + fast fqq (validated r14: bit-identical output)
__device__ __forceinline__ float prcp(float s) {
    float r;
    asm("rcp.approx.ftz.f32 %0, %1;" : "=f"(r) : "f"(s));
    float e = __fmaf_rn(-s, r, 1.0f);
    return __fmaf_rn(r, e, r);
}
__device__ __forceinline__ float fqqr(float x, float s, float r) {
    float y = __fmul_rn(x, r);
    float e = __fmaf_rn(-s, y, x);
    y = __fmaf_rn(e, r, y);
    return fminf(127.f, fmaxf(-128.f, rintf(y)));
}
__device__ __forceinline__ bf162 packbf(float lo, float hi) {
    unsigned u;
    asm("cvt.rn.bf16x2.f32 %0, %1, %2;" : "=r"(u) : "f"(hi), "f"(lo));
    return *(bf162*)&u;
}

// ---------------------------------------------------------------------------
// prep kernels
// ---------------------------------------------------------------------------

__global__ void prep1_k(const float* __restrict__ n1a, const float* __restrict__ n2a,
                        const float* __restrict__ g1,  const float* __restrict__ g2,
                        const float* __restrict__ w0,  const float* __restrict__ w1,
                        const float* __restrict__ w2,  const float* __restrict__ w3,
                        const float* __restrict__ w4,  const float* __restrict__ sc) {
    int role = blockIdx.y;
    int tid = threadIdx.x;
    if (role < 4) {
        if (blockIdx.x != 0) return;
        __shared__ float red[256];
        const float* src = (role == 0) ? n1a : (role == 1) ? n2a : (role == 2) ? g1 : g2;
        float* dst = (role == 0) ? g_v1a : (role == 1) ? g_v2a : (role == 2) ? g_g1 : g_g2;
        float m = 0.f;
        for (int i = tid; i < DIM; i += 256) m = fmaxf(m, fabsf(src[i]));
        red[tid] = m;
        __syncthreads();
        for (int s = 128; s > 0; s >>= 1) {
            if (tid < s) red[tid] = fmaxf(red[tid], red[tid + s]);
            __syncthreads();
        }
        float scv = __fadd_rn(__fdiv_rn(red[0], 127.f), 1e-8f);
        for (int i = tid; i < DIM; i += 256)
            dst[i] = __fmul_rn(scv, fqq(src[i], scv));
        return;
    }
    if (role == 9) {
        if (blockIdx.x != 0) return;
        float sc5 = sc[5], sc6 = sc[6];
        float q = (float)(tid - 128);
        float tq = __fmul_rn(sc5, q);
        float ge = __fmul_rn(__fmul_rn(0.5f, tq),
                   __fadd_rn(1.f, erff(__fmul_rn(tq, 0.70710678118654752f))));
        float qv = fqq(ge, sc6);
        bf16 b = __float2bfloat16_rn(qv);
        g_gelut[tid] = *(unsigned short*)&b;
        return;
    }
    int seg = role - 4;
    const float* w; int n;
    if (seg == 0)      { w = w0; n = NTOK * NTOK; }
    else if (seg == 1) { w = w1; n = RNK * DIM; }
    else if (seg == 2) { w = w2; n = HID * RNK; }
    else if (seg == 3) { w = w3; n = RNK * HID; }
    else               { w = w4; n = DIM * RNK; }
    float m = 0.f;
    for (int i = blockIdx.x * blockDim.x + tid; i < n; i += gridDim.x * blockDim.x)
        m = fmaxf(m, fabsf(w[i]));
#pragma unroll
    for (int o = 16; o; o >>= 1) m = fmaxf(m, __shfl_xor_sync(0xffffffffu, m, o));
    if ((tid & 31) == 0)
        atomicMax((int*)&g_absmax[seg], __float_as_int(m));
}

__global__ void quantw_all_k(const float* __restrict__ w0, const float* __restrict__ w1,
                             const float* __restrict__ w2, const float* __restrict__ w3,
                             const float* __restrict__ w4) {
    int seg = blockIdx.y;
    float s = wscale(seg);
    if (seg == 0) {
        for (int i = blockIdx.x * blockDim.x + threadIdx.x; i < 256 * KPAD;
             i += gridDim.x * blockDim.x) {
            int m = i >> 8, k = i & (KPAD - 1);
            float v = 0.f;
            if (m < NTOK && k < NTOK) v = fqq(w0[m * NTOK + k], s);
            g_qWattn[i] = __float2bfloat16_rn(v);
        }
        return;
    }
    const float* w; bf16* dst; int n;
    if (seg == 1)      { w = w1; dst = g_qW1vt; n = RNK * DIM; }
    else if (seg == 2) { w = w2; dst = g_qW1u;  n = HID * RNK; }
    else if (seg == 3) { w = w3; dst = g_qW2vt; n = RNK * HID; }
    else               { w = w4; dst = g_qW2u;  n = DIM * RNK; }
    for (int i = blockIdx.x * blockDim.x + threadIdx.x; i < n;
         i += gridDim.x * blockDim.x)
        dst[i] = __float2bfloat16_rn(fqq(w[i], s));
}

// stage 0: qa1t[b][d][n] = fq(x[b,n,d]*fqw(norm1_a)[d]+norm1_b[d], s0)/s0
__global__ void stage0_k(const float* __restrict__ x,
                         const float* __restrict__ nb1,
                         const float* __restrict__ sc) {
    __shared__ float tile[64][33];
    int d0 = blockIdx.x * 32, n0 = blockIdx.y * 64, b = blockIdx.z;
    float s0 = sc[0];
    float r0 = prcp(s0);
    int tx = threadIdx.x, ty = threadIdx.y;
#pragma unroll
    for (int r = 0; r < 8; ++r) {
        int nl = ty + r * 8;
        int n = n0 + nl, d = d0 + tx;
        float v = 0.f;
        if (n < NTOK) v = x[((long)b * NTOK + n) * DIM + d];
        tile[nl][tx] = v;
    }
    __syncthreads();
#pragma unroll
    for (int r = 0; r < 4; ++r) {
        int dl = ty + r * 8;
        int d = d0 + dl;
        float va = g_v1a[d], vb = nb1[d];
        int nl = tx * 2;
        float q0 = 0.f, q1 = 0.f;
        if (n0 + nl < NTOK)
            q0 = fqqr(__fadd_rn(__fmul_rn(tile[nl][dl], va), vb), s0, r0);
        if (n0 + nl + 1 < NTOK)
            q1 = fqqr(__fadd_rn(__fmul_rn(tile[nl + 1][dl], va), vb), s0, r0);
        *(bf162*)(g_qa1t + ((long)b * DIM + d) * KPAD + n0 + nl) = packbf(q0, q1);
    }
}

// attn tail: tokens 192..195 via exact f32 FMA (integers < 2^24 -> exact,
// bit-identical to the tensor-core path). One thread per (b, d).
__global__ void __launch_bounds__(256)
attn_tail_k(const float* __restrict__ sc, const float* __restrict__ attb,
            const float* __restrict__ xorg, const float* __restrict__ nb2) {
    __shared__ float wsm[4][256];
    int tid = threadIdx.x;
    for (int i = tid; i < 1024; i += 256) {
        int r = i >> 8, k = i & 255;
        wsm[r][k] = __bfloat162float(g_qWattn[(192 + r) * KPAD + k]);
    }
    __syncthreads();

    int t = blockIdx.x * 256 + tid;          // 0 .. 98303
    int b = t / DIM, d = t - b * DIM;
    const bf16* row = g_qa1t + ((long)b * DIM + d) * KPAD;

    float acc[4] = {0.f, 0.f, 0.f, 0.f};
#pragma unroll 4
    for (int k = 0; k < 256; k += 4) {
        uint2 pv = *(const uint2*)(row + k);
        bf162 p0 = *(bf162*)&pv.x, p1 = *(bf162*)&pv.y;
        float v0 = __bfloat162float(p0.x), v1 = __bfloat162float(p0.y);
        float v2 = __bfloat162float(p1.x), v3 = __bfloat162float(p1.y);
#pragma unroll
        for (int r = 0; r < 4; ++r) {
            float4 w = *(const float4*)&wsm[r][k];
            acc[r] = __fmaf_rn(v0, w.x, acc[r]);
            acc[r] = __fmaf_rn(v1, w.y, acc[r]);
            acc[r] = __fmaf_rn(v2, w.z, acc[r]);
            acc[r] = __fmaf_rn(v3, w.w, acc[r]);
        }
    }

    // STAGE-0 epilogue, scalar (op-for-op identical)
    float swp = sc[0] * wscale(0);
    float sc1 = sc[1], sc2 = sc[2], sc8 = sc[8];
    float r1 = prcp(sc1), r2 = prcp(sc2), r8 = prcp(sc8);
    float gg1 = g_g1[d], vv2 = g_v2a[d], nbd = nb2[d];
#pragma unroll
    for (int r = 0; r < 4; ++r) {
        int mm = 192 + r;
        float v = __fadd_rn(__fmul_rn(acc[r], swp), attb[mm]);
        float tv = __fmul_rn(__fmul_rn(sc1, fqqr(v, sc1, r1)), gg1);
        long idx = ((long)b * NTOK + mm) * DIM + d;
        float x1 = __fadd_rn(tv, xorg[idx]);
        float q8 = fqqr(x1, sc8, r8);
        g_qx1[idx] = __float2bfloat16_rn(q8);
        float h = __fadd_rn(__fmul_rn(__fmul_rn(sc8, q8), vv2), nbd);
        g_qa2[idx] = __float2bfloat16_rn(fqqr(h, sc2, r2));
    }
}

// ---------------------------------------------------------------------------
// bf16 HMMA GEMM core: BM x BN tile, WRxWC warps, 2-stage cp.async
// ---------------------------------------------------------------------------

__device__ __forceinline__ unsigned s2u(const void* p) {
    return (unsigned)__cvta_generic_to_shared(p);
}
__device__ __forceinline__ void cp16(void* d, const void* s) {
    asm volatile("cp.async.cg.shared.global [%0], [%1], 16;\n"
                 :: "r"(s2u(d)), "l"(s) : "memory");
}
__device__ __forceinline__ void cpcommit() {
    asm volatile("cp.async.commit_group;\n" ::: "memory");
}
__device__ __forceinline__ void cpwait0() {
    asm volatile("cp.async.wait_group 0;\n" ::: "memory");
}
__device__ __forceinline__ void ldsm4(unsigned* r, const void* p) {
    asm volatile("ldmatrix.sync.aligned.m8n8.x4.shared.b16 {%0,%1,%2,%3}, [%4];\n"
                 : "=r"(r[0]), "=r"(r[1]), "=r"(r[2]), "=r"(r[3]) : "r"(s2u(p)));
}
__device__ __forceinline__ void mma_bf16(float* c, const unsigned* a,
                                         unsigned b0, unsigned b1) {
    asm volatile(
        "mma.sync.aligned.m16n8k16.row.col.f32.bf16.bf16.f32 "
        "{%0,%1,%2,%3},{%4,%5,%6,%7},{%8,%9},{%0,%1,%2,%3};\n"
        : "+f"(c[0]), "+f"(c[1]), "+f"(c[2]), "+f"(c[3])
        : "r"(a[0]), "r"(a[1]), "r"(a[2]), "r"(a[3]), "r"(b0), "r"(b1));
}

__device__ __forceinline__ int swz(int row, int chunk) {
    return row * 128 + (((chunk ^ row) & 7) << 4);
}

// STAGE: 0=attn(+res/norm2), 1=fc1_vt, 2=fc1_u(+GELU LUT), 3=fc2_vt, 4=fc2_u(+out)
template <int STAGE, int BM, int BN, int WR, int WC, int OCC>
__global__ void __launch_bounds__(WR * WC * 32, OCC)
gemm_bf_k(int M, int N, int K,
          const float* __restrict__ sc,
          const float* __restrict__ bias,
          const float* __restrict__ xorg,
          const float* __restrict__ nb2,
          float* __restrict__ outf) {

    constexpr int THREADS = WR * WC * 32;
    constexpr int A_BYTES = BM * 128;
    constexpr int STAGE_BYTES = (BM + BN) * 128;
    constexpr int WM = BM / WR;
    constexpr int WN = BN / WC;
    constexpr int MI = WM / 16;
    constexpr int NJ = WN / 8;
    constexpr int NB = NJ / 2;
    constexpr int ACH = BM * 8 / THREADS;
    constexpr int BCH = BN * 8 / THREADS;

    extern __shared__ __align__(256) int8_t dsm[];
    __shared__ unsigned short s_lut[256];

    const int tid  = threadIdx.x;
    const int warp = tid >> 5, lane = tid & 31;
    const int wm = warp / WC, wn = warp % WC;
    const int m0 = blockIdx.y * BM;
    const int n0 = blockIdx.x * BN;
    const int bz = blockIdx.z;

    if (STAGE == 2 && tid < 256) s_lut[tid] = g_gelut[tid];

    const bf16* Ab;
    const bf16* Bb;
    if (STAGE == 0)      { Ab = g_qWattn; Bb = g_qa1t + (long)bz * DIM * KPAD; }
    else if (STAGE == 1) { Ab = g_qa2;    Bb = g_qW1vt; }
    else if (STAGE == 2) { Ab = g_qa3;    Bb = g_qW1u; }
    else if (STAGE == 3) { Ab = g_qa4;    Bb = g_qW2vt; }
    else                 { Ab = g_qa5;    Bb = g_qW2u; }

    const long rowBytes = (long)K * 2;

    const int aRowL = (tid * ACH) >> 3, aCbL = (tid * ACH) & 7;
    const int bRowL = (tid * BCH) >> 3, bCbL = (tid * BCH) & 7;

    const int8_t* agp = (const int8_t*)Ab + (long)(m0 + aRowL) * rowBytes + aCbL * 16;
    const int8_t* bgp = (const int8_t*)Bb + (long)(n0 + bRowL) * rowBytes + bCbL * 16;

    int sA[ACH], sB[BCH];
#pragma unroll
    for (int c = 0; c < ACH; ++c) sA[c] = swz(aRowL, aCbL + c);
#pragma unroll
    for (int c = 0; c < BCH; ++c) sB[c] = swz(bRowL, bCbL + c) + A_BYTES;

    auto loadTile = [&](int buf) {
        int8_t* base = dsm + buf * STAGE_BYTES;
#pragma unroll
        for (int c = 0; c < ACH; ++c) cp16(base + sA[c], agp + c * 16);
#pragma unroll
        for (int c = 0; c < BCH; ++c) cp16(base + sB[c], bgp + c * 16);
        cpcommit();
        agp += 128;
        bgp += 128;
    };

    float acc[MI][NJ][4];
#pragma unroll
    for (int i = 0; i < MI; ++i)
#pragma unroll
        for (int j = 0; j < NJ; ++j)
#pragma unroll
            for (int t = 0; t < 4; ++t) acc[i][j][t] = 0.f;

    const int ktiles = K >> 6;
    loadTile(0);

    const int aRow = lane & 15;
    const int bRow = (lane & 7) + ((lane >> 3) & 1) * 8;
    const int cLane = lane >> 4;

    for (int kt = 0; kt < ktiles; ++kt) {
        cpwait0();
        __syncthreads();               // orders buffer reuse (and s_lut fill)
        if (kt + 1 < ktiles) loadTile((kt + 1) & 1);

        int8_t* as = dsm + (kt & 1) * STAGE_BYTES;
        int8_t* bs = as + A_BYTES;

#pragma unroll
        for (int ks = 0; ks < 4; ++ks) {
            unsigned a[MI][4], b[NB][4];
#pragma unroll
            for (int i = 0; i < MI; ++i)
                ldsm4(a[i], as + swz(wm * WM + i * 16 + aRow, ks * 2 + cLane));
#pragma unroll
            for (int jp = 0; jp < NB; ++jp)
                ldsm4(b[jp], bs + swz(wn * WN + jp * 16 + bRow, ks * 2 + cLane));
#pragma unroll
            for (int jp = 0; jp < NB; ++jp)
#pragma unroll
                for (int i = 0; i < MI; ++i) {
                    mma_bf16(acc[i][jp * 2 + 0], a[i], b[jp][0], b[jp][2]);
                    mma_bf16(acc[i][jp * 2 + 1], a[i], b[jp][1], b[jp][3]);
                }
        }
    }

    // ---- epilogue ----
    const float sc1 = sc[1], sc2 = sc[2], sc3 = sc[3], sc4 = sc[4];
    const float sc5 = sc[5], sc6 = sc[6], sc7 = sc[7], sc8 = sc[8], sc9 = sc[9];
    const float r1 = prcp(sc1), r2 = prcp(sc2), r3 = prcp(sc3);
    const float r4 = prcp(sc4), r5 = prcp(sc5);
    const float r7 = prcp(sc7), r8 = prcp(sc8), r9 = prcp(sc9);
    float swp;
    if (STAGE == 0)      swp = sc[0] * wscale(0);
    else if (STAGE == 1) swp = sc2 * wscale(1);
    else if (STAGE == 2) swp = sc4 * wscale(2);
    else if (STAGE == 3) swp = sc6 * wscale(3);
    else                 swp = sc7 * wscale(4);

#pragma unroll
    for (int i = 0; i < MI; ++i) {
        int mrow = m0 + wm * WM + i * 16 + (lane >> 2);
#pragma unroll
        for (int j = 0; j < NJ; ++j) {
            int nn = n0 + wn * WN + j * 8 + ((lane & 3) << 1);
#pragma unroll
            for (int h = 0; h < 2; ++h) {
                int mm = mrow + h * 8;
                if (mm >= M) continue;
                float a0 = acc[i][j][h * 2 + 0];
                float a1 = acc[i][j][h * 2 + 1];

                if (STAGE == 0) {
                    float bm = bias[mm];
                    float v0 = __fadd_rn(__fmul_rn(a0, swp), bm);
                    float v1 = __fadd_rn(__fmul_rn(a1, swp), bm);
                    float t0 = __fmul_rn(__fmul_rn(sc1, fqqr(v0, sc1, r1)), g_g1[nn]);
                    float t1 = __fmul_rn(__fmul_rn(sc1, fqqr(v1, sc1, r1)), g_g1[nn + 1]);
                    long idx = ((long)bz * NTOK + mm) * DIM + nn;
                    float2 xo = *(const float2*)(xorg + idx);
                    float q80 = fqqr(__fadd_rn(t0, xo.x), sc8, r8);
                    float q81 = fqqr(__fadd_rn(t1, xo.y), sc8, r8);
                    *(bf162*)(g_qx1 + idx) = packbf(q80, q81);
                    float x10 = __fmul_rn(sc8, q80), x11 = __fmul_rn(sc8, q81);
                    float h0 = __fadd_rn(__fmul_rn(x10, g_v2a[nn]),     nb2[nn]);
                    float h1 = __fadd_rn(__fmul_rn(x11, g_v2a[nn + 1]), nb2[nn + 1]);
                    *(bf162*)(g_qa2 + idx) =
                        packbf(fqqr(h0, sc2, r2), fqqr(h1, sc2, r2));
                } else if (STAGE == 1 || STAGE == 3) {
                    bf16* dst = (STAGE == 1) ? g_qa3 : g_qa5;
                    float scq = (STAGE == 1) ? sc4 : sc7;
                    float rq  = (STAGE == 1) ? r4  : r7;
                    float v0 = __fadd_rn(__fmul_rn(a0, swp), bias[nn]);
                    float v1 = __fadd_rn(__fmul_rn(a1, swp), bias[nn + 1]);
                    *(bf162*)(dst + (long)mm * RNK + nn) =
                        packbf(fqqr(v0, scq, rq), fqqr(v1, scq, rq));
                } else if (STAGE == 2) {
                    float v0 = __fadd_rn(__fmul_rn(a0, swp), bias[nn]);
                    float v1 = __fadd_rn(__fmul_rn(a1, swp), bias[nn + 1]);
                    int i0 = (int)fqqr(v0, sc5, r5) + 128;
                    int i1 = (int)fqqr(v1, sc5, r5) + 128;
                    unsigned u = (unsigned)s_lut[i0] | ((unsigned)s_lut[i1] << 16);
                    *(unsigned*)(g_qa4 + (long)mm * HID + nn) = u;
                } else {
                    float v0 = __fadd_rn(__fmul_rn(a0, swp), bias[nn]);
                    float v1 = __fadd_rn(__fmul_rn(a1, swp), bias[nn + 1]);
                    float t0 = __fmul_rn(__fmul_rn(sc3, fqqr(v0, sc3, r3)), g_g2[nn]);
                    float t1 = __fmul_rn(__fmul_rn(sc3, fqqr(v1, sc3, r3)), g_g2[nn + 1]);
                    long idx = (long)mm * DIM + nn;
                    bf162 qx = *(const bf162*)(g_qx1 + idx);
                    float rr0 = __fadd_rn(t0, __fmul_rn(sc8, __bfloat162float(qx.x)));
                    float rr1 = __fadd_rn(t1, __fmul_rn(sc8, __bfloat162float(qx.y)));
                    float2 o;
                    o.x = __fmul_rn(sc9, fqqr(rr0, sc9, r9));
                    o.y = __fmul_rn(sc9, fqqr(rr1, sc9, r9));
                    *(float2*)(outf + idx) = o;
                }
            }
        }
    }
}

constexpr int SMEM_ATTN = 2 * (64 + 64) * 128;     // 32768
constexpr int SMEM_FC   = 2 * (128 + 128) * 128;   // 65536

} // anonymous namespace

// ---------------------------------------------------------------------------
extern "C" void kernel_launch(void* const* d_in, const int* in_sizes, int n_in,
                              void* d_out, int out_size) {
    const float* x    = (const float*)d_in[0];
    const float* n1a  = (const float*)d_in[1];
    const float* n1b  = (const float*)d_in[2];
    const float* attw = (const float*)d_in[3];
    const float* attb = (const float*)d_in[4];
    const float* g1   = (const float*)d_in[5];
    const float* n2a  = (const float*)d_in[6];
    const float* n2b  = (const float*)d_in[7];
    const float* w1vt = (const float*)d_in[8];
    const float* b1vt = (const float*)d_in[9];
    const float* w1u  = (const float*)d_in[10];
    const float* b1u  = (const float*)d_in[11];
    const float* w2vt = (const float*)d_in[12];
    const float* b2vt = (const float*)d_in[13];
    const float* w2u  = (const float*)d_in[14];
    const float* b2u  = (const float*)d_in[15];
    const float* g2   = (const float*)d_in[16];
    const float* sc   = (const float*)d_in[17];
    float* out = (float*)d_out;

    cudaFuncSetAttribute((const void*)gemm_bf_k<0, 64, 64, 2, 4, 6>,
                         cudaFuncAttributeMaxDynamicSharedMemorySize, SMEM_ATTN);
    cudaFuncSetAttribute((const void*)gemm_bf_k<1, 128, 128, 4, 4, 2>,
                         cudaFuncAttributeMaxDynamicSharedMemorySize, SMEM_FC);
    cudaFuncSetAttribute((const void*)gemm_bf_k<2, 128, 128, 4, 4, 2>,
                         cudaFuncAttributeMaxDynamicSharedMemorySize, SMEM_FC);
    cudaFuncSetAttribute((const void*)gemm_bf_k<3, 128, 128, 4, 4, 2>,
                         cudaFuncAttributeMaxDynamicSharedMemorySize, SMEM_FC);
    cudaFuncSetAttribute((const void*)gemm_bf_k<4, 128, 128, 4, 4, 2>,
                         cudaFuncAttributeMaxDynamicSharedMemorySize, SMEM_FC);

    prep1_k<<<dim3(96, 10), 256>>>(n1a, n2a, g1, g2, attw, w1vt, w1u, w2vt, w2u, sc);
    quantw_all_k<<<dim3(128, 5), 256>>>(attw, w1vt, w1u, w2vt, w2u);

    {   // stage 0: norm1 + fq(s0), transposed/padded to [b][d][256]
        dim3 grid(DIM / 32, KPAD / 64, BATCH);
        dim3 blk(32, 8);
        stage0_k<<<grid, blk>>>(x, n1b, sc);
    }
    {   // attn main: tokens 0-191 (3 full m-tiles, zero waste)
        dim3 grid(DIM / 64, 3, BATCH);
        gemm_bf_k<0, 64, 64, 2, 4, 6><<<grid, 256, SMEM_ATTN>>>(
            NTOK, DIM, KPAD, sc, attb, x, n2b, nullptr);
    }
    {   // attn tail: tokens 192-195 via exact FMA
        attn_tail_k<<<(BATCH * DIM) / 256, 256>>>(sc, attb, x, n2b);
    }
    {   // fc1_vt — 128x128 @2 CTAs/SM, 512 threads
        dim3 grid(RNK / 128, (int)(TROWS / 128), 1);
        gemm_bf_k<1, 128, 128, 4, 4, 2><<<grid, 512, SMEM_FC>>>(
            (int)TROWS, RNK, DIM, sc, b1vt, x, n2b, nullptr);
    }
    {   // fc1_u (+GELU via LUT)
        dim3 grid(HID / 128, (int)(TROWS / 128), 1);
        gemm_bf_k<2, 128, 128, 4, 4, 2><<<grid, 512, SMEM_FC>>>(
            (int)TROWS, HID, RNK, sc, b1u, x, n2b, nullptr);
    }
    {   // fc2_vt
        dim3 grid(RNK / 128, (int)(TROWS / 128), 1);
        gemm_bf_k<3, 128, 128, 4, 4, 2><<<grid, 512, SMEM_FC>>>(
            (int)TROWS, RNK, HID, sc, b2vt, x, n2b, nullptr);
    }
    {   // fc2_u + gamma2 + residual -> out
        dim3 grid(DIM / 128, (int)(TROWS / 128), 1);
        gemm_bf_k<4, 128, 128, 4, 4, 2><<<grid, 512, SMEM_FC>>>(
            (int)TROWS, DIM, RNK, sc, b2u, x, n2b, out);
    }
}

// round 17
// speedup vs baseline: 1.0597x; 1.0597x over previous
#include <cuda_runtime.h>
#include <cuda_bf16.h>
#include <cstdint>
#include <math.h>

// ---------------------------------------------------------------------------
// QLayer_Block round 17: bf16 HMMA GEMMs (exact integer math).
// attn split into BM=64 x2 tiles (rows 0-127) + BM=96 tile at moff=128
// (rows 128-223, valid to 195) -> 12.5% less MMA work, 25% less B traffic,
// no extra global reads (r16's separate tail kernel reverted).
// Keeps: fast-div fqq (r14), GELU LUT (r15), per-stage configs (r11).
// ---------------------------------------------------------------------------

namespace {

typedef __nv_bfloat16 bf16;
typedef __nv_bfloat162 bf162;

constexpr int BATCH = 128;
constexpr int NTOK  = 196;
constexpr int DIM   = 768;
constexpr int HID   = 3072;
constexpr int RNK   = 384;
constexpr int KPAD  = 256;
constexpr long TROWS = (long)BATCH * NTOK;   // 25088

// ---- device scratch (integer-valued bf16) ----
__device__ __align__(256) bf16 g_qWattn[256 * KPAD];
__device__ __align__(256) bf16 g_qW1vt[RNK * DIM];
__device__ __align__(256) bf16 g_qW1u [HID * RNK];
__device__ __align__(256) bf16 g_qW2vt[RNK * HID];
__device__ __align__(256) bf16 g_qW2u [DIM * RNK];

__device__ __align__(256) float g_v1a[DIM];
__device__ __align__(256) float g_v2a[DIM];
__device__ __align__(256) float g_g1 [DIM];
__device__ __align__(256) float g_g2 [DIM];
__device__ float g_absmax[8];
__device__ __align__(256) unsigned short g_gelut[256];   // bf16 bits of fq(gelu)

__device__ __align__(256) bf16 g_qa1t[(long)BATCH * DIM * KPAD]; // [b][d][npad]
__device__ __align__(256) bf16 g_qx1 [TROWS * DIM];
__device__ __align__(256) bf16 g_qa2 [TROWS * DIM];
__device__ __align__(256) bf16 g_qa3 [TROWS * RNK];
__device__ __align__(256) bf16 g_qa4 [TROWS * HID];
__device__ __align__(256) bf16 g_qa5 [TROWS * RNK];

// exact fqq (prep paths only)
__device__ __forceinline__ float fqq(float x, float s) {
    float r = rintf(__fdiv_rn(x, s));
    return fminf(127.f, fmaxf(-128.f, r));
}
__device__ __forceinline__ float wscale(int slot) {
    return __fadd_rn(__fdiv_rn(g_absmax[slot], 127.f), 1e-8f);
}

// Newton-refined reciprocal + fast fqq (validated r14: bit-identical output)
__device__ __forceinline__ float prcp(float s) {
    float r;
    asm("rcp.approx.ftz.f32 %0, %1;" : "=f"(r) : "f"(s));
    float e = __fmaf_rn(-s, r, 1.0f);
    return __fmaf_rn(r, e, r);
}
__device__ __forceinline__ float fqqr(float x, float s, float r) {
    float y = __fmul_rn(x, r);
    float e = __fmaf_rn(-s, y, x);
    y = __fmaf_rn(e, r, y);
    return fminf(127.f, fmaxf(-128.f, rintf(y)));
}
// integer variant (LUT index): cvt.rni + int clamp
__device__ __forceinline__ int fqqi(float x, float s, float r) {
    float y = __fmul_rn(x, r);
    float e = __fmaf_rn(-s, y, x);
    y = __fmaf_rn(e, r, y);
    int q = __float2int_rn(y);
    return min(127, max(-128, q));
}
__device__ __forceinline__ bf162 packbf(float lo, float hi) {
    unsigned u;
    asm("cvt.rn.bf16x2.f32 %0, %1, %2;" : "=r"(u) : "f"(hi), "f"(lo));
    return *(bf162*)&u;
}

// ---------------------------------------------------------------------------
// prep kernels
// ---------------------------------------------------------------------------

__global__ void prep1_k(const float* __restrict__ n1a, const float* __restrict__ n2a,
                        const float* __restrict__ g1,  const float* __restrict__ g2,
                        const float* __restrict__ w0,  const float* __restrict__ w1,
                        const float* __restrict__ w2,  const float* __restrict__ w3,
                        const float* __restrict__ w4,  const float* __restrict__ sc) {
    int role = blockIdx.y;
    int tid = threadIdx.x;
    if (role < 4) {
        if (blockIdx.x != 0) return;
        __shared__ float red[256];
        const float* src = (role == 0) ? n1a : (role == 1) ? n2a : (role == 2) ? g1 : g2;
        float* dst = (role == 0) ? g_v1a : (role == 1) ? g_v2a : (role == 2) ? g_g1 : g_g2;
        float m = 0.f;
        for (int i = tid; i < DIM; i += 256) m = fmaxf(m, fabsf(src[i]));
        red[tid] = m;
        __syncthreads();
        for (int s = 128; s > 0; s >>= 1) {
            if (tid < s) red[tid] = fmaxf(red[tid], red[tid + s]);
            __syncthreads();
        }
        float scv = __fadd_rn(__fdiv_rn(red[0], 127.f), 1e-8f);
        for (int i = tid; i < DIM; i += 256)
            dst[i] = __fmul_rn(scv, fqq(src[i], scv));
        return;
    }
    if (role == 9) {
        if (blockIdx.x != 0) return;
        float sc5 = sc[5], sc6 = sc[6];
        float q = (float)(tid - 128);
        float tq = __fmul_rn(sc5, q);
        float ge = __fmul_rn(__fmul_rn(0.5f, tq),
                   __fadd_rn(1.f, erff(__fmul_rn(tq, 0.70710678118654752f))));
        float qv = fqq(ge, sc6);
        bf16 b = __float2bfloat16_rn(qv);
        g_gelut[tid] = *(unsigned short*)&b;
        return;
    }
    int seg = role - 4;
    const float* w; int n;
    if (seg == 0)      { w = w0; n = NTOK * NTOK; }
    else if (seg == 1) { w = w1; n = RNK * DIM; }
    else if (seg == 2) { w = w2; n = HID * RNK; }
    else if (seg == 3) { w = w3; n = RNK * HID; }
    else               { w = w4; n = DIM * RNK; }
    float m = 0.f;
    for (int i = blockIdx.x * blockDim.x + tid; i < n; i += gridDim.x * blockDim.x)
        m = fmaxf(m, fabsf(w[i]));
#pragma unroll
    for (int o = 16; o; o >>= 1) m = fmaxf(m, __shfl_xor_sync(0xffffffffu, m, o));
    if ((tid & 31) == 0)
        atomicMax((int*)&g_absmax[seg], __float_as_int(m));
}

__global__ void quantw_all_k(const float* __restrict__ w0, const float* __restrict__ w1,
                             const float* __restrict__ w2, const float* __restrict__ w3,
                             const float* __restrict__ w4) {
    int seg = blockIdx.y;
    float s = wscale(seg);
    if (seg == 0) {
        for (int i = blockIdx.x * blockDim.x + threadIdx.x; i < 256 * KPAD;
             i += gridDim.x * blockDim.x) {
            int m = i >> 8, k = i & (KPAD - 1);
            float v = 0.f;
            if (m < NTOK && k < NTOK) v = fqq(w0[m * NTOK + k], s);
            g_qWattn[i] = __float2bfloat16_rn(v);
        }
        return;
    }
    const float* w; bf16* dst; int n;
    if (seg == 1)      { w = w1; dst = g_qW1vt; n = RNK * DIM; }
    else if (seg == 2) { w = w2; dst = g_qW1u;  n = HID * RNK; }
    else if (seg == 3) { w = w3; dst = g_qW2vt; n = RNK * HID; }
    else               { w = w4; dst = g_qW2u;  n = DIM * RNK; }
    for (int i = blockIdx.x * blockDim.x + threadIdx.x; i < n;
         i += gridDim.x * blockDim.x)
        dst[i] = __float2bfloat16_rn(fqq(w[i], s));
}

// stage 0: qa1t[b][d][n] = fq(x[b,n,d]*fqw(norm1_a)[d]+norm1_b[d], s0)/s0
__global__ void stage0_k(const float* __restrict__ x,
                         const float* __restrict__ nb1,
                         const float* __restrict__ sc) {
    __shared__ float tile[64][33];
    int d0 = blockIdx.x * 32, n0 = blockIdx.y * 64, b = blockIdx.z;
    float s0 = sc[0];
    float r0 = prcp(s0);
    int tx = threadIdx.x, ty = threadIdx.y;
#pragma unroll
    for (int r = 0; r < 8; ++r) {
        int nl = ty + r * 8;
        int n = n0 + nl, d = d0 + tx;
        float v = 0.f;
        if (n < NTOK) v = x[((long)b * NTOK + n) * DIM + d];
        tile[nl][tx] = v;
    }
    __syncthreads();
#pragma unroll
    for (int r = 0; r < 4; ++r) {
        int dl = ty + r * 8;
        int d = d0 + dl;
        float va = g_v1a[d], vb = nb1[d];
        int nl = tx * 2;
        float q0 = 0.f, q1 = 0.f;
        if (n0 + nl < NTOK)
            q0 = fqqr(__fadd_rn(__fmul_rn(tile[nl][dl], va), vb), s0, r0);
        if (n0 + nl + 1 < NTOK)
            q1 = fqqr(__fadd_rn(__fmul_rn(tile[nl + 1][dl], va), vb), s0, r0);
        *(bf162*)(g_qa1t + ((long)b * DIM + d) * KPAD + n0 + nl) = packbf(q0, q1);
    }
}

// ---------------------------------------------------------------------------
// bf16 HMMA GEMM core: BM x BN tile, WRxWC warps, 2-stage cp.async
// ---------------------------------------------------------------------------

__device__ __forceinline__ unsigned s2u(const void* p) {
    return (unsigned)__cvta_generic_to_shared(p);
}
__device__ __forceinline__ void cp16(void* d, const void* s) {
    asm volatile("cp.async.cg.shared.global [%0], [%1], 16;\n"
                 :: "r"(s2u(d)), "l"(s) : "memory");
}
__device__ __forceinline__ void cpcommit() {
    asm volatile("cp.async.commit_group;\n" ::: "memory");
}
__device__ __forceinline__ void cpwait0() {
    asm volatile("cp.async.wait_group 0;\n" ::: "memory");
}
__device__ __forceinline__ void ldsm4(unsigned* r, const void* p) {
    asm volatile("ldmatrix.sync.aligned.m8n8.x4.shared.b16 {%0,%1,%2,%3}, [%4];\n"
                 : "=r"(r[0]), "=r"(r[1]), "=r"(r[2]), "=r"(r[3]) : "r"(s2u(p)));
}
__device__ __forceinline__ void mma_bf16(float* c, const unsigned* a,
                                         unsigned b0, unsigned b1) {
    asm volatile(
        "mma.sync.aligned.m16n8k16.row.col.f32.bf16.bf16.f32 "
        "{%0,%1,%2,%3},{%4,%5,%6,%7},{%8,%9},{%0,%1,%2,%3};\n"
        : "+f"(c[0]), "+f"(c[1]), "+f"(c[2]), "+f"(c[3])
        : "r"(a[0]), "r"(a[1]), "r"(a[2]), "r"(a[3]), "r"(b0), "r"(b1));
}

__device__ __forceinline__ int swz(int row, int chunk) {
    return row * 128 + (((chunk ^ row) & 7) << 4);
}

// STAGE: 0=attn(+res/norm2), 1=fc1_vt, 2=fc1_u(+GELU LUT), 3=fc2_vt, 4=fc2_u(+out)
// moff: extra m-row offset (attn rows-128..223 tile).
template <int STAGE, int BM, int BN, int WR, int WC, int OCC>
__global__ void __launch_bounds__(WR * WC * 32, OCC)
gemm_bf_k(int M, int N, int K, int moff,
          const float* __restrict__ sc,
          const float* __restrict__ bias,
          const float* __restrict__ xorg,
          const float* __restrict__ nb2,
          float* __restrict__ outf) {

    constexpr int THREADS = WR * WC * 32;
    constexpr int RSTEP = THREADS >> 3;       // loader row stride per chunk
    constexpr int A_BYTES = BM * 128;
    constexpr int STAGE_BYTES = (BM + BN) * 128;
    constexpr int WM = BM / WR;
    constexpr int WN = BN / WC;
    constexpr int MI = WM / 16;
    constexpr int NJ = WN / 8;
    constexpr int NB = NJ / 2;
    constexpr int ACH = BM / RSTEP;
    constexpr int BCH = BN / RSTEP;

    extern __shared__ __align__(256) int8_t dsm[];
    __shared__ unsigned short s_lut[256];

    const int tid  = threadIdx.x;
    const int warp = tid >> 5, lane = tid & 31;
    const int wm = warp / WC, wn = warp % WC;
    const int m0 = blockIdx.y * BM + moff;
    const int n0 = blockIdx.x * BN;
    const int bz = blockIdx.z;

    if (STAGE == 2 && tid < 256) s_lut[tid] = g_gelut[tid];

    const bf16* Ab;
    const bf16* Bb;
    if (STAGE == 0)      { Ab = g_qWattn; Bb = g_qa1t + (long)bz * DIM * KPAD; }
    else if (STAGE == 1) { Ab = g_qa2;    Bb = g_qW1vt; }
    else if (STAGE == 2) { Ab = g_qa3;    Bb = g_qW1u; }
    else if (STAGE == 3) { Ab = g_qa4;    Bb = g_qW2vt; }
    else                 { Ab = g_qa5;    Bb = g_qW2u; }

    const long rowBytes = (long)K * 2;
    const long step = (long)RSTEP * rowBytes;

    // strided loader: thread handles chunks (tid + c*THREADS); col = tid&7
    const int rowL = tid >> 3, colL = tid & 7;
    const int8_t* agp = (const int8_t*)Ab + (long)(m0 + rowL) * rowBytes + colL * 16;
    const int8_t* bgp = (const int8_t*)Bb + (long)(n0 + rowL) * rowBytes + colL * 16;

    int sA[ACH], sB[BCH];
#pragma unroll
    for (int c = 0; c < ACH; ++c) sA[c] = swz(rowL + c * RSTEP, colL);
#pragma unroll
    for (int c = 0; c < BCH; ++c) sB[c] = swz(rowL + c * RSTEP, colL) + A_BYTES;

    auto loadTile = [&](int buf) {
        int8_t* base = dsm + buf * STAGE_BYTES;
#pragma unroll
        for (int c = 0; c < ACH; ++c) cp16(base + sA[c], agp + c * step);
#pragma unroll
        for (int c = 0; c < BCH; ++c) cp16(base + sB[c], bgp + c * step);
        cpcommit();
        agp += 128;
        bgp += 128;
    };

    float acc[MI][NJ][4];
#pragma unroll
    for (int i = 0; i < MI; ++i)
#pragma unroll
        for (int j = 0; j < NJ; ++j)
#pragma unroll
            for (int t = 0; t < 4; ++t) acc[i][j][t] = 0.f;

    const int ktiles = K >> 6;
    loadTile(0);

    const int aRow = lane & 15;
    const int bRow = (lane & 7) + ((lane >> 3) & 1) * 8;
    const int cLane = lane >> 4;

    for (int kt = 0; kt < ktiles; ++kt) {
        cpwait0();
        __syncthreads();               // orders buffer reuse (and s_lut fill)
        if (kt + 1 < ktiles) loadTile((kt + 1) & 1);

        int8_t* as = dsm + (kt & 1) * STAGE_BYTES;
        int8_t* bs = as + A_BYTES;

#pragma unroll
        for (int ks = 0; ks < 4; ++ks) {
            unsigned a[MI][4], b[NB][4];
#pragma unroll
            for (int i = 0; i < MI; ++i)
                ldsm4(a[i], as + swz(wm * WM + i * 16 + aRow, ks * 2 + cLane));
#pragma unroll
            for (int jp = 0; jp < NB; ++jp)
                ldsm4(b[jp], bs + swz(wn * WN + jp * 16 + bRow, ks * 2 + cLane));
#pragma unroll
            for (int jp = 0; jp < NB; ++jp)
#pragma unroll
                for (int i = 0; i < MI; ++i) {
                    mma_bf16(acc[i][jp * 2 + 0], a[i], b[jp][0], b[jp][2]);
                    mma_bf16(acc[i][jp * 2 + 1], a[i], b[jp][1], b[jp][3]);
                }
        }
    }

    // ---- epilogue ----
    const float sc1 = sc[1], sc2 = sc[2], sc3 = sc[3], sc4 = sc[4];
    const float sc5 = sc[5], sc6 = sc[6], sc7 = sc[7], sc8 = sc[8], sc9 = sc[9];
    const float r1 = prcp(sc1), r2 = prcp(sc2), r3 = prcp(sc3);
    const float r4 = prcp(sc4), r5 = prcp(sc5);
    const float r7 = prcp(sc7), r8 = prcp(sc8), r9 = prcp(sc9);
    float swp;
    if (STAGE == 0)      swp = sc[0] * wscale(0);
    else if (STAGE == 1) swp = sc2 * wscale(1);
    else if (STAGE == 2) swp = sc4 * wscale(2);
    else if (STAGE == 3) swp = sc6 * wscale(3);
    else                 swp = sc7 * wscale(4);

#pragma unroll
    for (int i = 0; i < MI; ++i) {
        int mrow = m0 + wm * WM + i * 16 + (lane >> 2);
#pragma unroll
        for (int j = 0; j < NJ; ++j) {
            int nn = n0 + wn * WN + j * 8 + ((lane & 3) << 1);
#pragma unroll
            for (int h = 0; h < 2; ++h) {
                int mm = mrow + h * 8;
                if (mm >= M) continue;
                float a0 = acc[i][j][h * 2 + 0];
                float a1 = acc[i][j][h * 2 + 1];

                if (STAGE == 0) {
                    float bm = bias[mm];
                    float v0 = __fadd_rn(__fmul_rn(a0, swp), bm);
                    float v1 = __fadd_rn(__fmul_rn(a1, swp), bm);
                    float t0 = __fmul_rn(__fmul_rn(sc1, fqqr(v0, sc1, r1)), g_g1[nn]);
                    float t1 = __fmul_rn(__fmul_rn(sc1, fqqr(v1, sc1, r1)), g_g1[nn + 1]);
                    long idx = ((long)bz * NTOK + mm) * DIM + nn;
                    float2 xo = *(const float2*)(xorg + idx);
                    float q80 = fqqr(__fadd_rn(t0, xo.x), sc8, r8);
                    float q81 = fqqr(__fadd_rn(t1, xo.y), sc8, r8);
                    *(bf162*)(g_qx1 + idx) = packbf(q80, q81);
                    float x10 = __fmul_rn(sc8, q80), x11 = __fmul_rn(sc8, q81);
                    float h0 = __fadd_rn(__fmul_rn(x10, g_v2a[nn]),     nb2[nn]);
                    float h1 = __fadd_rn(__fmul_rn(x11, g_v2a[nn + 1]), nb2[nn + 1]);
                    *(bf162*)(g_qa2 + idx) =
                        packbf(fqqr(h0, sc2, r2), fqqr(h1, sc2, r2));
                } else if (STAGE == 1 || STAGE == 3) {
                    bf16* dst = (STAGE == 1) ? g_qa3 : g_qa5;
                    float scq = (STAGE == 1) ? sc4 : sc7;
                    float rq  = (STAGE == 1) ? r4  : r7;
                    float v0 = __fadd_rn(__fmul_rn(a0, swp), bias[nn]);
                    float v1 = __fadd_rn(__fmul_rn(a1, swp), bias[nn + 1]);
                    *(bf162*)(dst + (long)mm * RNK + nn) =
                        packbf(fqqr(v0, scq, rq), fqqr(v1, scq, rq));
                } else if (STAGE == 2) {
                    float v0 = __fadd_rn(__fmul_rn(a0, swp), bias[nn]);
                    float v1 = __fadd_rn(__fmul_rn(a1, swp), bias[nn + 1]);
                    int i0 = fqqi(v0, sc5, r5) + 128;
                    int i1 = fqqi(v1, sc5, r5) + 128;
                    unsigned u = (unsigned)s_lut[i0] | ((unsigned)s_lut[i1] << 16);
                    *(unsigned*)(g_qa4 + (long)mm * HID + nn) = u;
                } else {
                    float v0 = __fadd_rn(__fmul_rn(a0, swp), bias[nn]);
                    float v1 = __fadd_rn(__fmul_rn(a1, swp), bias[nn + 1]);
                    float t0 = __fmul_rn(__fmul_rn(sc3, fqqr(v0, sc3, r3)), g_g2[nn]);
                    float t1 = __fmul_rn(__fmul_rn(sc3, fqqr(v1, sc3, r3)), g_g2[nn + 1]);
                    long idx = (long)mm * DIM + nn;
                    bf162 qx = *(const bf162*)(g_qx1 + idx);
                    float rr0 = __fadd_rn(t0, __fmul_rn(sc8, __bfloat162float(qx.x)));
                    float rr1 = __fadd_rn(t1, __fmul_rn(sc8, __bfloat162float(qx.y)));
                    float2 o;
                    o.x = __fmul_rn(sc9, fqqr(rr0, sc9, r9));
                    o.y = __fmul_rn(sc9, fqqr(rr1, sc9, r9));
                    *(float2*)(outf + idx) = o;
                }
            }
        }
    }
}

constexpr int SMEM_ATTN  = 2 * (64 + 64) * 128;    // 32768
constexpr int SMEM_ATTN2 = 2 * (96 + 64) * 128;    // 40960
constexpr int SMEM_FC    = 2 * (128 + 128) * 128;  // 65536

} // anonymous namespace

// ---------------------------------------------------------------------------
extern "C" void kernel_launch(void* const* d_in, const int* in_sizes, int n_in,
                              void* d_out, int out_size) {
    const float* x    = (const float*)d_in[0];
    const float* n1a  = (const float*)d_in[1];
    const float* n1b  = (const float*)d_in[2];
    const float* attw = (const float*)d_in[3];
    const float* attb = (const float*)d_in[4];
    const float* g1   = (const float*)d_in[5];
    const float* n2a  = (const float*)d_in[6];
    const float* n2b  = (const float*)d_in[7];
    const float* w1vt = (const float*)d_in[8];
    const float* b1vt = (const float*)d_in[9];
    const float* w1u  = (const float*)d_in[10];
    const float* b1u  = (const float*)d_in[11];
    const float* w2vt = (const float*)d_in[12];
    const float* b2vt = (const float*)d_in[13];
    const float* w2u  = (const float*)d_in[14];
    const float* b2u  = (const float*)d_in[15];
    const float* g2   = (const float*)d_in[16];
    const float* sc   = (const float*)d_in[17];
    float* out = (float*)d_out;

    cudaFuncSetAttribute((const void*)gemm_bf_k<0, 64, 64, 2, 4, 6>,
                         cudaFuncAttributeMaxDynamicSharedMemorySize, SMEM_ATTN);
    cudaFuncSetAttribute((const void*)gemm_bf_k<0, 96, 64, 2, 4, 4>,
                         cudaFuncAttributeMaxDynamicSharedMemorySize, SMEM_ATTN2);
    cudaFuncSetAttribute((const void*)gemm_bf_k<1, 128, 128, 4, 4, 2>,
                         cudaFuncAttributeMaxDynamicSharedMemorySize, SMEM_FC);
    cudaFuncSetAttribute((const void*)gemm_bf_k<2, 128, 128, 4, 4, 2>,
                         cudaFuncAttributeMaxDynamicSharedMemorySize, SMEM_FC);
    cudaFuncSetAttribute((const void*)gemm_bf_k<3, 128, 128, 4, 4, 2>,
                         cudaFuncAttributeMaxDynamicSharedMemorySize, SMEM_FC);
    cudaFuncSetAttribute((const void*)gemm_bf_k<4, 128, 128, 4, 4, 2>,
                         cudaFuncAttributeMaxDynamicSharedMemorySize, SMEM_FC);

    prep1_k<<<dim3(96, 10), 256>>>(n1a, n2a, g1, g2, attw, w1vt, w1u, w2vt, w2u, sc);
    quantw_all_k<<<dim3(128, 5), 256>>>(attw, w1vt, w1u, w2vt, w2u);

    {   // stage 0: norm1 + fq(s0), transposed/padded to [b][d][256]
        dim3 grid(DIM / 32, KPAD / 64, BATCH);
        dim3 blk(32, 8);
        stage0_k<<<grid, blk>>>(x, n1b, sc);
    }
    {   // attn part A: tokens 0-127 (two fully-used 64-row tiles)
        dim3 grid(DIM / 64, 2, BATCH);
        gemm_bf_k<0, 64, 64, 2, 4, 6><<<grid, 256, SMEM_ATTN>>>(
            NTOK, DIM, KPAD, 0, sc, attb, x, n2b, nullptr);
    }
    {   // attn part B: tokens 128-195 in one 96-row tile at moff=128
        dim3 grid(DIM / 64, 1, BATCH);
        gemm_bf_k<0, 96, 64, 2, 4, 4><<<grid, 256, SMEM_ATTN2>>>(
            NTOK, DIM, KPAD, 128, sc, attb, x, n2b, nullptr);
    }
    {   // fc1_vt — 128x128 @2 CTAs/SM, 512 threads
        dim3 grid(RNK / 128, (int)(TROWS / 128), 1);
        gemm_bf_k<1, 128, 128, 4, 4, 2><<<grid, 512, SMEM_FC>>>(
            (int)TROWS, RNK, DIM, 0, sc, b1vt, x, n2b, nullptr);
    }
    {   // fc1_u (+GELU via LUT)
        dim3 grid(HID / 128, (int)(TROWS / 128), 1);
        gemm_bf_k<2, 128, 128, 4, 4, 2><<<grid, 512, SMEM_FC>>>(
            (int)TROWS, HID, RNK, 0, sc, b1u, x, n2b, nullptr);
    }
    {   // fc2_vt
        dim3 grid(RNK / 128, (int)(TROWS / 128), 1);
        gemm_bf_k<3, 128, 128, 4, 4, 2><<<grid, 512, SMEM_FC>>>(
            (int)TROWS, RNK, HID, 0, sc, b2vt, x, n2b, nullptr);
    }
    {   // fc2_u + gamma2 + residual -> out
        dim3 grid(DIM / 128, (int)(TROWS / 128), 1);
        gemm_bf_k<4, 128, 128, 4, 4, 2><<<grid, 512, SMEM_FC>>>(
            (int)TROWS, DIM, RNK, 0, sc, b2u, x, n2b, out);
    }
}